// round 14
// baseline (speedup 1.0000x reference)
#include <cuda_runtime.h>
#include <cuda_bf16.h>
#include <math.h>
#include <stdint.h>

#define N_NODES 4096
#define F_DIM   512
#define H_DIM   256

// ---------------- scratch (static device allocations; no runtime alloc) ----------
__device__ __align__(128) __nv_bfloat16 g_xhi[N_NODES * F_DIM];
__device__ __align__(128) __nv_bfloat16 g_xlo[N_NODES * F_DIM];
__device__ __align__(128) __nv_bfloat16 g_wThi[1310720];
__device__ __align__(128) __nv_bfloat16 g_wTlo[1310720];
__device__ __align__(128) float g_bcat[2560];
__device__ __align__(128) __nv_bfloat16 g_xmshi[N_NODES * 1024];
__device__ __align__(128) __nv_bfloat16 g_xmslo[N_NODES * 1024];
__device__ __align__(128) __nv_bfloat16 g_fcat[N_NODES * 1024];
__device__ __align__(128) __nv_bfloat16 g_M1b[(size_t)N_NODES * N_NODES];
__device__ __align__(128) __nv_bfloat16 g_AnT[(size_t)N_NODES * N_NODES];
__device__ __align__(128) float g_t0[N_NODES * 1024];          // split-K partials (enc2)
__device__ __align__(128) __nv_bfloat16 g_t0T[1024 * N_NODES];
__device__ __align__(128) __nv_bfloat16 g_t1hi[N_NODES * 1024];
__device__ __align__(128) __nv_bfloat16 g_t1lo[N_NODES * 1024];
__device__ __align__(128) __nv_bfloat16 g_t2T[512 * N_NODES];
__device__ __align__(128) float g_ssum[N_NODES];
__device__ __align__(128) float g_rn[N_NODES];
__device__ __align__(128) float g_dis[N_NODES];
__device__ __align__(128) float g_rnparts[96 * N_NODES];   // [0,64) row partials, [64,96) mirror col partials
__device__ __align__(128) float g_colpart[256 * N_NODES];

// ================= low-level helpers (sm_80+ features only) =================
__device__ __forceinline__ uint32_t smem_u32(const void* p) {
    uint32_t a;
    asm("{ .reg .u64 t; cvta.to.shared.u64 t, %1; cvt.u32.u64 %0, t; }" : "=r"(a) : "l"(p));
    return a;
}

#define CP_ASYNC_CG(dst, src) \
    asm volatile("cp.async.cg.shared.global [%0], [%1], 16;" :: "r"(dst), "l"(src))
#define CP_COMMIT() asm volatile("cp.async.commit_group;" ::: "memory")
#define CP_WAIT(n)  asm volatile("cp.async.wait_group %0;" :: "n"(n) : "memory")

__device__ __forceinline__ void ldmat_x4(uint32_t& r0, uint32_t& r1, uint32_t& r2, uint32_t& r3,
                                         uint32_t addr) {
    asm volatile("ldmatrix.sync.aligned.m8n8.x4.shared.b16 {%0,%1,%2,%3}, [%4];"
                 : "=r"(r0), "=r"(r1), "=r"(r2), "=r"(r3) : "r"(addr));
}

__device__ __forceinline__ void mma16816f(float* c, const uint32_t* a, const uint32_t* b) {
    asm volatile(
        "mma.sync.aligned.m16n8k16.row.col.f32.bf16.bf16.f32 "
        "{%0,%1,%2,%3}, {%4,%5,%6,%7}, {%8,%9}, {%0,%1,%2,%3};"
        : "+f"(c[0]), "+f"(c[1]), "+f"(c[2]), "+f"(c[3])
        : "r"(a[0]), "r"(a[1]), "r"(a[2]), "r"(a[3]), "r"(b[0]), "r"(b[1]));
}

#define BM 128
#define BK 32
#define LDSH 40   // BK + 8 halves padding

// ================= generalized bf16 HMMA NT GEMM =================
// C[M,N] = A[M,K] @ B[N,K]^T. bf16 K-major inputs.
// SPLIT==3: near-fp32 via AhiBhi + AhiBlo + AloBhi (BNT=128 only). 3-stage pipeline.
// SPLIT==1: 4-stage pipeline.
// EPI: 0=store fp32
//      6=*dis[row]+bias+relu, store hi/lo bf16
//      7=*dis[row], smem-transposed bf16 store to Ohi (ldc = transposed row length)
//      8=+bias, store hi/lo bf16 only
template<int SPLIT, int EPI, int BNT>
__global__ __launch_bounds__(256)
void mma_nt(const __nv_bfloat16* __restrict__ Ahi, const __nv_bfloat16* __restrict__ Alo,
            const __nv_bfloat16* __restrict__ Bhi, const __nv_bfloat16* __restrict__ Blo,
            float* __restrict__ C, __nv_bfloat16* __restrict__ Ohi, __nv_bfloat16* __restrict__ Olo,
            int M, int N, int K, int lda, int ldb, int ldc,
            const float* __restrict__ bias, const float* __restrict__ dis,
            long zA, long zB, long zC)
{
    constexpr int STAGES = (SPLIT == 1) ? 4 : 3;
    constexpr int WN     = BNT / 4;
    constexpr int NFR    = WN / 8;
    constexpr int TILEA  = BM * LDSH;
    constexpr int TILEB  = BNT * LDSH;
    constexpr int STAGE  = ((SPLIT == 3) ? 2 : 1) * (TILEA + TILEB);
    extern __shared__ __nv_bfloat16 smB[];

    const int tid  = threadIdx.x;
    const int wid  = tid >> 5;
    const int lane = tid & 31;
    const int wm = (wid & 1) * 64;
    const int wn = (wid >> 1) * WN;
    const int bm = blockIdx.y * BM;
    const int bn = blockIdx.x * BNT;

    const __nv_bfloat16* Ag  = Ahi + (size_t)blockIdx.z * zA + (size_t)bm * lda;
    const __nv_bfloat16* Bg  = Bhi + (size_t)blockIdx.z * zB + (size_t)bn * ldb;
    const __nv_bfloat16* Agl = (SPLIT == 3) ? Alo + (size_t)blockIdx.z * zA + (size_t)bm * lda : nullptr;
    const __nv_bfloat16* Bgl = (SPLIT == 3) ? Blo + (size_t)blockIdx.z * zB + (size_t)bn * ldb : nullptr;
    float* Cz = C + (size_t)blockIdx.z * zC;

    const uint32_t s_base = smem_u32(smB);
    const int lr0 = tid >> 2;
    const int lc  = (tid & 3) * 8;

    float acc[4][NFR][4];
    #pragma unroll
    for (int i = 0; i < 4; ++i)
        #pragma unroll
        for (int j = 0; j < NFR; ++j)
            #pragma unroll
            for (int q = 0; q < 4; ++q) acc[i][j][q] = 0.f;

    const int nt = K / BK;

    auto load_stage = [&](int st, int t) {
        const size_t kb = (size_t)t * BK + lc;
        const uint32_t sb = s_base + (uint32_t)(st * STAGE) * 2;
        #pragma unroll
        for (int h = 0; h < 2; ++h) {
            const int r = lr0 + h * 64;
            const uint32_t so = (uint32_t)(r * LDSH + lc) * 2;
            CP_ASYNC_CG(sb + so, Ag + (size_t)r * lda + kb);
            if (SPLIT == 3)
                CP_ASYNC_CG(sb + (uint32_t)(TILEA + TILEB) * 2 + so, Agl + (size_t)r * lda + kb);
        }
        #pragma unroll
        for (int h = 0; h < BNT / 64; ++h) {
            const int r = lr0 + h * 64;
            const uint32_t so = (uint32_t)(TILEA + r * LDSH + lc) * 2;
            CP_ASYNC_CG(sb + so, Bg + (size_t)r * ldb + kb);
            if (SPLIT == 3)
                CP_ASYNC_CG(sb + (uint32_t)(TILEA + TILEB) * 2 + so, Bgl + (size_t)r * ldb + kb);
        }
    };

    #pragma unroll
    for (int s = 0; s < STAGES - 1; ++s) { load_stage(s, s); CP_COMMIT(); }

    for (int t = 0; t < nt; ++t) {
        CP_WAIT(STAGES - 2);
        __syncthreads();
        if (t + STAGES - 1 < nt) { load_stage((t + STAGES - 1) % STAGES, t + STAGES - 1); CP_COMMIT(); }

        const uint32_t sb = s_base + (uint32_t)((t % STAGES) * STAGE) * 2;
        #pragma unroll
        for (int kk = 0; kk < BK; kk += 16) {
            uint32_t ah[4][4], al[4][4];
            #pragma unroll
            for (int mf = 0; mf < 4; ++mf) {
                int row = wm + mf * 16 + (lane & 15);
                uint32_t off = (uint32_t)(row * LDSH + kk + ((lane >> 4) << 3)) * 2;
                ldmat_x4(ah[mf][0], ah[mf][1], ah[mf][2], ah[mf][3], sb + off);
                if (SPLIT == 3)
                    ldmat_x4(al[mf][0], al[mf][1], al[mf][2], al[mf][3],
                             sb + (uint32_t)(TILEA + TILEB) * 2 + off);
            }
            uint32_t bh[NFR][2], bl[NFR][2];
            #pragma unroll
            for (int nf2 = 0; nf2 < NFR / 2; ++nf2) {
                int row = wn + nf2 * 16 + (lane & 7) + (((lane >> 4) & 1) << 3);
                uint32_t off = (uint32_t)(TILEA + row * LDSH + kk + (((lane >> 3) & 1) << 3)) * 2;
                uint32_t r0, r1, r2, r3;
                ldmat_x4(r0, r1, r2, r3, sb + off);
                bh[nf2 * 2 + 0][0] = r0; bh[nf2 * 2 + 0][1] = r1;
                bh[nf2 * 2 + 1][0] = r2; bh[nf2 * 2 + 1][1] = r3;
                if (SPLIT == 3) {
                    ldmat_x4(r0, r1, r2, r3, sb + (uint32_t)(TILEA + TILEB) * 2 + off);
                    bl[nf2 * 2 + 0][0] = r0; bl[nf2 * 2 + 0][1] = r1;
                    bl[nf2 * 2 + 1][0] = r2; bl[nf2 * 2 + 1][1] = r3;
                }
            }
            #pragma unroll
            for (int mf = 0; mf < 4; ++mf)
                #pragma unroll
                for (int nf = 0; nf < NFR; ++nf) {
                    mma16816f(acc[mf][nf], ah[mf], bh[nf]);
                    if (SPLIT == 3) {
                        mma16816f(acc[mf][nf], ah[mf], bl[nf]);
                        mma16816f(acc[mf][nf], al[mf], bh[nf]);
                    }
                }
        }
        // no trailing sync: next iter's loads are gated by the top-of-loop barrier
    }

    if (EPI == 7) {
        // ---- transposed bf16 epilogue: Ohi[(bn+c)*ldc + bm+r] = acc[r][c] * dis[bm+r] ----
        __syncthreads();   // all warps done reading pipeline smem
        __nv_bfloat16* st = smB;   // BNT x 136 halves
        #pragma unroll
        for (int mf = 0; mf < 4; ++mf) {
            int rl = wm + mf * 16 + (lane >> 2);
            float d0 = dis[bm + rl], d1 = dis[bm + rl + 8];
            #pragma unroll
            for (int nf = 0; nf < NFR; ++nf) {
                int cl = wn + nf * 8 + (lane & 3) * 2;
                st[(cl + 0) * 136 + rl]     = __float2bfloat16(acc[mf][nf][0] * d0);
                st[(cl + 1) * 136 + rl]     = __float2bfloat16(acc[mf][nf][1] * d0);
                st[(cl + 0) * 136 + rl + 8] = __float2bfloat16(acc[mf][nf][2] * d1);
                st[(cl + 1) * 136 + rl + 8] = __float2bfloat16(acc[mf][nf][3] * d1);
            }
        }
        __syncthreads();
        __nv_bfloat16* Ohz = Ohi + (size_t)blockIdx.z * zC;
        for (int it = tid; it < BNT * 16; it += 256) {
            int c = it >> 4, ch = it & 15;
            uint4 v = *(uint4*)&st[c * 136 + ch * 8];
            *(uint4*)(Ohz + (size_t)(bn + c) * ldc + bm + ch * 8) = v;
        }
        return;
    }

    // ---- register epilogues ----
    #pragma unroll
    for (int mf = 0; mf < 4; ++mf) {
        #pragma unroll
        for (int nf = 0; nf < NFR; ++nf) {
            int rg = bm + wm + mf * 16 + (lane >> 2);
            int cg = bn + wn + nf * 8 + (lane & 3) * 2;
            float v0 = acc[mf][nf][0], v1 = acc[mf][nf][1];
            float v2 = acc[mf][nf][2], v3 = acc[mf][nf][3];
            if (EPI == 8) {
                float b0 = bias[cg], b1 = bias[cg + 1];
                v0 += b0; v1 += b1; v2 += b0; v3 += b1;
            }
            if (EPI == 6) {
                float d0 = dis[rg], d1 = dis[rg + 8];
                float b0 = bias[cg], b1 = bias[cg + 1];
                v0 = fmaxf(fmaf(v0, d0, b0), 0.f);
                v1 = fmaxf(fmaf(v1, d0, b1), 0.f);
                v2 = fmaxf(fmaf(v2, d1, b0), 0.f);
                v3 = fmaxf(fmaf(v3, d1, b1), 0.f);
            }
            if (EPI == 6 || EPI == 8) {
                __nv_bfloat162 h01, l01, h23, l23;
                h01.x = __float2bfloat16(v0); h01.y = __float2bfloat16(v1);
                l01.x = __float2bfloat16(v0 - __bfloat162float(h01.x));
                l01.y = __float2bfloat16(v1 - __bfloat162float(h01.y));
                h23.x = __float2bfloat16(v2); h23.y = __float2bfloat16(v3);
                l23.x = __float2bfloat16(v2 - __bfloat162float(h23.x));
                l23.y = __float2bfloat16(v3 - __bfloat162float(h23.y));
                *(__nv_bfloat162*)(Ohi + (size_t)rg * ldc + cg) = h01;
                *(__nv_bfloat162*)(Olo + (size_t)rg * ldc + cg) = l01;
                *(__nv_bfloat162*)(Ohi + (size_t)(rg + 8) * ldc + cg) = h23;
                *(__nv_bfloat162*)(Olo + (size_t)(rg + 8) * ldc + cg) = l23;
            } else {
                float2 p0; p0.x = v0; p0.y = v1;
                float2 p1; p1.x = v2; p1.y = v3;
                *(float2*)(Cz + (size_t)rg * ldc + cg) = p0;
                *(float2*)(Cz + (size_t)(rg + 8) * ldc + cg) = p1;
            }
        }
    }
}

// ================= symmetric gram + ws + rn partials (triangle grid, 4-stage) =========
__global__ __launch_bounds__(256)
void gram_sym(const __nv_bfloat16* __restrict__ A, __nv_bfloat16* __restrict__ M1b,
              const float* __restrict__ ssum, float* __restrict__ rnpart,
              float* __restrict__ colsq2)
{
    constexpr int NFR = 8;
    constexpr int STAGES = 4;
    constexpr int TILEA = 128 * LDSH, TILEB = 256 * LDSH, STAGE = TILEA + TILEB;
    extern __shared__ __nv_bfloat16 smB[];
    __nv_bfloat16* mir = smB;                              // 256 x 136 halves
    float* colsq = (float*)((char*)smB + 69632);           // 256 floats

    int L = blockIdx.x, p = 0;
    while (L >= 2 * (16 - p)) { L -= 2 * (16 - p); ++p; }
    int m, b;
    if (L < 16 - p) { m = 2 * p; b = p + L; }
    else            { m = 2 * p + 1; b = p + L - (16 - p); }
    const int bm = m * 128, bn = b * 256;
    const bool above = (2 * b >= m + 1);

    const int tid  = threadIdx.x;
    const int wid  = tid >> 5;
    const int lane = tid & 31;
    const int wm = (wid & 1) * 64;
    const int wn = (wid >> 1) * 64;

    const __nv_bfloat16* Ag = A + (size_t)bm * 1024;
    const __nv_bfloat16* Bg = A + (size_t)bn * 1024;
    const uint32_t s_base = smem_u32(smB);
    const int lr0 = tid >> 2;
    const int lc  = (tid & 3) * 8;

    float acc[4][NFR][4];
    #pragma unroll
    for (int i = 0; i < 4; ++i)
        #pragma unroll
        for (int j = 0; j < NFR; ++j)
            #pragma unroll
            for (int q = 0; q < 4; ++q) acc[i][j][q] = 0.f;

    auto load_stage = [&](int st, int t) {
        const size_t kb = (size_t)t * BK + lc;
        const uint32_t sb = s_base + (uint32_t)(st * STAGE) * 2;
        #pragma unroll
        for (int h = 0; h < 2; ++h) {
            const int r = lr0 + h * 64;
            CP_ASYNC_CG(sb + (uint32_t)(r * LDSH + lc) * 2, Ag + (size_t)r * 1024 + kb);
        }
        #pragma unroll
        for (int h = 0; h < 4; ++h) {
            const int r = lr0 + h * 64;
            CP_ASYNC_CG(sb + (uint32_t)(TILEA + r * LDSH + lc) * 2, Bg + (size_t)r * 1024 + kb);
        }
    };

    #pragma unroll
    for (int s = 0; s < STAGES - 1; ++s) { load_stage(s, s); CP_COMMIT(); }

    for (int t = 0; t < 32; ++t) {
        CP_WAIT(STAGES - 2);
        __syncthreads();
        if (t + STAGES - 1 < 32) { load_stage((t + STAGES - 1) % STAGES, t + STAGES - 1); CP_COMMIT(); }

        const uint32_t sb = s_base + (uint32_t)((t % STAGES) * STAGE) * 2;
        #pragma unroll
        for (int kk = 0; kk < BK; kk += 16) {
            uint32_t ah[4][4];
            #pragma unroll
            for (int mf = 0; mf < 4; ++mf) {
                int row = wm + mf * 16 + (lane & 15);
                uint32_t off = (uint32_t)(row * LDSH + kk + ((lane >> 4) << 3)) * 2;
                ldmat_x4(ah[mf][0], ah[mf][1], ah[mf][2], ah[mf][3], sb + off);
            }
            uint32_t bh[NFR][2];
            #pragma unroll
            for (int nf2 = 0; nf2 < NFR / 2; ++nf2) {
                int row = wn + nf2 * 16 + (lane & 7) + (((lane >> 4) & 1) << 3);
                uint32_t off = (uint32_t)(TILEA + row * LDSH + kk + (((lane >> 3) & 1) << 3)) * 2;
                uint32_t r0, r1, r2, r3;
                ldmat_x4(r0, r1, r2, r3, sb + off);
                bh[nf2 * 2 + 0][0] = r0; bh[nf2 * 2 + 0][1] = r1;
                bh[nf2 * 2 + 1][0] = r2; bh[nf2 * 2 + 1][1] = r3;
            }
            #pragma unroll
            for (int mf = 0; mf < 4; ++mf)
                #pragma unroll
                for (int nf = 0; nf < NFR; ++nf)
                    mma16816f(acc[mf][nf], ah[mf], bh[nf]);
        }
    }
    __syncthreads();   // protect smem reuse (mir/colsq alias pipeline buffers)

    if (above) colsq[tid] = 0.f;
    __syncthreads();

    float rs[8];
    #pragma unroll
    for (int i = 0; i < 8; ++i) rs[i] = 0.f;
    float cs0[NFR], cs1[NFR];
    #pragma unroll
    for (int i = 0; i < NFR; ++i) { cs0[i] = 0.f; cs1[i] = 0.f; }

    #pragma unroll
    for (int mf = 0; mf < 4; ++mf) {
        #pragma unroll
        for (int nf = 0; nf < NFR; ++nf) {
            int rl = wm + mf * 16 + (lane >> 2);
            int cl = wn + nf * 8 + (lane & 3) * 2;
            int rg = bm + rl, cg = bn + cl;
            float sc0 = ssum[cg], sc1 = ssum[cg + 1];
            float sr0 = ssum[rg], sr1 = ssum[rg + 8];
            float v0 = expf(2.f * acc[mf][nf][0] - sr0 - sc0);
            float v1 = expf(2.f * acc[mf][nf][1] - sr0 - sc1);
            float v2 = expf(2.f * acc[mf][nf][2] - sr1 - sc0);
            float v3 = expf(2.f * acc[mf][nf][3] - sr1 - sc1);
            rs[mf * 2 + 0] = fmaf(v0, v0, fmaf(v1, v1, rs[mf * 2 + 0]));
            rs[mf * 2 + 1] = fmaf(v2, v2, fmaf(v3, v3, rs[mf * 2 + 1]));
            __nv_bfloat162 h01, h23;
            h01.x = __float2bfloat16(v0); h01.y = __float2bfloat16(v1);
            h23.x = __float2bfloat16(v2); h23.y = __float2bfloat16(v3);
            *(__nv_bfloat162*)(M1b + (size_t)rg * N_NODES + cg) = h01;
            *(__nv_bfloat162*)(M1b + (size_t)(rg + 8) * N_NODES + cg) = h23;
            if (above) {
                cs0[nf] = fmaf(v0, v0, fmaf(v2, v2, cs0[nf]));
                cs1[nf] = fmaf(v1, v1, fmaf(v3, v3, cs1[nf]));
                mir[(cl + 0) * 136 + rl]     = h01.x;
                mir[(cl + 1) * 136 + rl]     = h01.y;
                mir[(cl + 0) * 136 + rl + 8] = h23.x;
                mir[(cl + 1) * 136 + rl + 8] = h23.y;
            }
        }
    }

    #pragma unroll
    for (int i = 0; i < 8; ++i) {
        rs[i] += __shfl_xor_sync(0xffffffffu, rs[i], 1);
        rs[i] += __shfl_xor_sync(0xffffffffu, rs[i], 2);
    }
    if ((lane & 3) == 0) {
        int pidx = b * 4 + (wid >> 1);
        #pragma unroll
        for (int mf = 0; mf < 4; ++mf) {
            int row = bm + wm + mf * 16 + (lane >> 2);
            rnpart[(size_t)pidx * N_NODES + row]     = rs[mf * 2 + 0];
            rnpart[(size_t)pidx * N_NODES + row + 8] = rs[mf * 2 + 1];
        }
    }

    if (above) {
        #pragma unroll
        for (int nf = 0; nf < NFR; ++nf) {
            #pragma unroll
            for (int o = 4; o < 32; o <<= 1) {
                cs0[nf] += __shfl_xor_sync(0xffffffffu, cs0[nf], o);
                cs1[nf] += __shfl_xor_sync(0xffffffffu, cs1[nf], o);
            }
        }
        if (lane < 4) {
            #pragma unroll
            for (int nf = 0; nf < NFR; ++nf) {
                atomicAdd(&colsq[wn + nf * 8 + lane * 2], cs0[nf]);
                atomicAdd(&colsq[wn + nf * 8 + lane * 2 + 1], cs1[nf]);
            }
        }
        __syncthreads();
        #pragma unroll 4
        for (int it = 0; it < 64; ++it) {
            int c = it * 4 + (tid >> 6);
            uint32_t vv = *(uint32_t*)&mir[c * 136 + (tid & 63) * 2];
            *(uint32_t*)(M1b + (size_t)(bn + c) * N_NODES + bm + (tid & 63) * 2) = vv;
        }
        colsq2[(size_t)m * N_NODES + bn + tid] = colsq[tid];
    }
}

// ---------------- batched weight prep: 6 transposes+splits in one launch ----------------
__global__ void wprep_kernel(const float* __restrict__ Wm, const float* __restrict__ Ws,
                             const float* __restrict__ mW0, const float* __restrict__ sW0,
                             const float* __restrict__ mW1, const float* __restrict__ sW1,
                             __nv_bfloat16* __restrict__ wThi, __nv_bfloat16* __restrict__ wTlo)
{
    const int z = blockIdx.z;
    const float* in; int C; long off;
    switch (z) {
        case 0:  in = Wm;  C = 512; off = 0;       break;
        case 1:  in = Ws;  C = 512; off = 262144;  break;
        case 2:  in = mW0; C = 512; off = 524288;  break;
        case 3:  in = sW0; C = 512; off = 786432;  break;
        case 4:  in = mW1; C = 256; off = 1048576; break;
        default: in = sW1; C = 256; off = 1179648; break;
    }
    if (blockIdx.x * 32 >= C) return;
    const int R = 512;
    __shared__ float t[32][33];
    int r0 = blockIdx.y * 32, c0 = blockIdx.x * 32;
    int tx = threadIdx.x, ty = threadIdx.y;
    #pragma unroll
    for (int j = 0; j < 4; ++j)
        t[ty + j * 8][tx] = in[(size_t)(r0 + ty + j * 8) * C + c0 + tx];
    __syncthreads();
    #pragma unroll
    for (int j = 0; j < 4; ++j) {
        int c = c0 + ty + j * 8;
        float v = t[tx][ty + j * 8];
        __nv_bfloat16 h = __float2bfloat16(v);
        __nv_bfloat16 l = __float2bfloat16(v - __bfloat162float(h));
        wThi[off + (size_t)c * R + r0 + tx] = h;
        wTlo[off + (size_t)c * R + r0 + tx] = l;
    }
}

__global__ void split_kernel(const float* __restrict__ in, __nv_bfloat16* __restrict__ ohi,
                             __nv_bfloat16* __restrict__ olo, int n)
{
    int idx = blockIdx.x * 256 + threadIdx.x;
    if (idx < n) {
        float v = in[idx];
        __nv_bfloat16 h = __float2bfloat16(v);
        ohi[idx] = h;
        olo[idx] = __float2bfloat16(v - __bfloat162float(h));
    }
}

__global__ void concat_bias_kernel(const float* bm, const float* bs, const float* mb0,
                                   const float* sb0, const float* mb1, const float* sb1,
                                   float* __restrict__ bcat)
{
    for (int i = threadIdx.x; i < 2560; i += blockDim.x) {
        float v;
        if (i < 512)        v = bm[i];
        else if (i < 1024)  v = bs[i - 512];
        else if (i < 1536)  v = mb0[i - 1024];
        else if (i < 2048)  v = sb0[i - 1536];
        else if (i < 2304)  v = mb1[i - 2048];
        else                v = sb1[i - 2304];
        bcat[i] = v;
    }
}

// ---------------- block reduction ----------------
__device__ __forceinline__ float blockReduceSum(float v, float* sh) {
    __syncthreads();
    int lane = threadIdx.x & 31, wid = threadIdx.x >> 5;
    #pragma unroll
    for (int o = 16; o; o >>= 1) v += __shfl_down_sync(0xffffffffu, v, o);
    if (lane == 0) sh[wid] = v;
    __syncthreads();
    if (wid == 0) {
        float r = (lane < ((blockDim.x + 31) >> 5)) ? sh[lane] : 0.f;
        #pragma unroll
        for (int o = 16; o; o >>= 1) r += __shfl_down_sync(0xffffffffu, r, o);
        if (lane == 0) sh[0] = r;
    }
    __syncthreads();
    return sh[0];
}

// ---------------- per-row stats from xms hi/lo: fcat = [m_hat||cs_hat], ssum ----
__global__ void rowstats_kernel(const __nv_bfloat16* __restrict__ xmshi,
                                const __nv_bfloat16* __restrict__ xmslo,
                                __nv_bfloat16* __restrict__ fcat, float* __restrict__ ssum)
{
    __shared__ float sh[32];
    int row = blockIdx.x;
    const __nv_bfloat16* hi = xmshi + (size_t)row * 1024;
    const __nv_bfloat16* lo = xmslo + (size_t)row * 1024;
    float s1 = 0.f, s2 = 0.f, s3 = 0.f;
    for (int j = threadIdx.x; j < F_DIM; j += blockDim.x) {
        float a = __bfloat162float(hi[j]) + __bfloat162float(lo[j]);
        s1 = fmaf(a, a, s1);
        float xs = __bfloat162float(hi[512 + j]) + __bfloat162float(lo[512 + j]);
        float e = expf(xs); s2 = fmaf(e, e, s2); s3 += e;
    }
    s1 = blockReduceSum(s1, sh);
    s2 = blockReduceSum(s2, sh);
    s3 = blockReduceSum(s3, sh);
    float dm = fmaxf(sqrtf(s1), 1e-12f);
    float dc = fmaxf(sqrtf(s2), 1e-12f);
    if (threadIdx.x == 0) ssum[row] = s1 / (dm * dm) + s3 / dc;
    float rdm = 1.f / dm;
    float rqc = rsqrtf(dc);
    for (int j = threadIdx.x; j < F_DIM; j += blockDim.x) {
        float a = __bfloat162float(hi[j]) + __bfloat162float(lo[j]);
        float xs = __bfloat162float(hi[512 + j]) + __bfloat162float(lo[512 + j]);
        fcat[(size_t)row * 1024 + j]       = __float2bfloat16(a * rdm);
        fcat[(size_t)row * 1024 + 512 + j] = __float2bfloat16(expf(0.5f * xs) * rqc);
    }
}

__global__ void rnreduce_kernel(const float* __restrict__ rnparts, float* __restrict__ rn) {
    int row = blockIdx.x * 256 + threadIdx.x;
    float s = 0.f;
    #pragma unroll
    for (int p = 0; p < 96; ++p) s += rnparts[(size_t)p * N_NODES + row];
    rn[row] = 1.f / fmaxf(sqrtf(s), 1e-12f);
}

// ---------------- fused adjacency + bf16-transpose + column partials ----------------
__global__ __launch_bounds__(256)
void adjT_kernel(const __nv_bfloat16* __restrict__ M1b, const float* __restrict__ rn,
                 const float* __restrict__ ne, const float* __restrict__ epsm,
                 const float* __restrict__ beta, const float* __restrict__ delta,
                 __nv_bfloat16* __restrict__ AnT, float* __restrict__ colpart)
{
    __shared__ __nv_bfloat16 tileT[64][66];
    const int c0 = blockIdx.x * 64, r0 = blockIdx.y * 64;
    const int t = threadIdx.x;
    const int jl = t & 63, ig = t >> 6;
    const int j = c0 + jl;
    const float b = beta[0], d = delta[0];
    float s = 0.f;
    #pragma unroll 4
    for (int k = 0; k < 16; ++k) {
        const int il = ig + 4 * k;
        const int i = r0 + il;
        const size_t idx = (size_t)i * N_NODES + j;
        float w = __bfloat162float(M1b[idx]) * rn[i];
        float tt = (1.f - b) * w + b * ne[idx];
        tt = fminf(fmaxf(tt, 1e-6f), 1.f - 1e-6f);
        float e = fminf(fmaxf(epsm[idx], 1e-6f), 1.f - 1e-6f);
        float num = tt * e;
        float sg = num / (num + (1.f - tt) * (1.f - e));
        float a = (sg > d) ? sg : 0.f;
        if (i == j && !(a > 0.f)) a += 1.f;
        tileT[il][jl] = __float2bfloat16(a);
        s += a;
    }
    colpart[(size_t)(blockIdx.y * 4 + ig) * N_NODES + j] = s;
    __syncthreads();
    const int il2 = t & 63;
    #pragma unroll
    for (int jj = t >> 6; jj < 64; jj += 4)
        AnT[(size_t)(c0 + jj) * N_NODES + r0 + il2] = tileT[il2][jj];
}

__global__ void colsum2_kernel(const float* __restrict__ part, float* __restrict__ dis) {
    int j = blockIdx.x * 256 + threadIdx.x;
    float s = 0.f;
    for (int p = 0; p < 256; ++p) s += part[(size_t)p * N_NODES + j];
    dis[j] = (s > 0.f) ? (1.f / sqrtf(s)) : 0.f;
}

// ---------------- split-K reduce + dis + bias + relu + z-split output ----------------
__global__ void reduce_out_kernel(const float* __restrict__ part, const float* __restrict__ bias,
                                  const float* __restrict__ dis, float* __restrict__ out)
{
    int idx = blockIdx.x * 256 + threadIdx.x;   // over 4096*512
    int row = idx >> 9, col = idx & 511;
    float v = fmaf(part[idx] + part[idx + N_NODES * 512], dis[row], bias[col]);
    v = fmaxf(v, 0.f);
    out[(size_t)(col >> 8) * (N_NODES * H_DIM) + (size_t)row * H_DIM + (col & 255)] = v;
}

// ---------------- host ----------------
extern "C" void kernel_launch(void* const* d_in, const int* in_sizes, int n_in,
                              void* d_out, int out_size)
{
    const float* x        = (const float*)d_in[0];
    const float* new_edge = (const float*)d_in[1];
    const float* beta     = (const float*)d_in[2];
    const float* delta    = (const float*)d_in[3];
    const float* eps      = (const float*)d_in[4];
    const float* Wm       = (const float*)d_in[5];
    const float* bm       = (const float*)d_in[6];
    const float* Ws       = (const float*)d_in[7];
    const float* bs       = (const float*)d_in[8];
    const float* mW0      = (const float*)d_in[9];
    const float* mb0      = (const float*)d_in[10];
    const float* mW1      = (const float*)d_in[11];
    const float* mb1      = (const float*)d_in[12];
    const float* sW0      = (const float*)d_in[13];
    const float* sb0      = (const float*)d_in[14];
    const float* sW1      = (const float*)d_in[15];
    const float* sb1      = (const float*)d_in[16];
    float* out = (float*)d_out;

    float *t0, *ssum, *rn, *dis, *rnparts, *colpart, *bcat;
    __nv_bfloat16 *xhi, *xlo, *wThi, *wTlo, *xmshi, *xmslo, *fcat, *M1b, *AnT, *t0T, *t1hi, *t1lo, *t2T;
    cudaGetSymbolAddress((void**)&xhi, g_xhi);
    cudaGetSymbolAddress((void**)&xlo, g_xlo);
    cudaGetSymbolAddress((void**)&wThi, g_wThi);
    cudaGetSymbolAddress((void**)&wTlo, g_wTlo);
    cudaGetSymbolAddress((void**)&bcat, g_bcat);
    cudaGetSymbolAddress((void**)&xmshi, g_xmshi);
    cudaGetSymbolAddress((void**)&xmslo, g_xmslo);
    cudaGetSymbolAddress((void**)&fcat, g_fcat);
    cudaGetSymbolAddress((void**)&M1b, g_M1b);
    cudaGetSymbolAddress((void**)&AnT, g_AnT);
    cudaGetSymbolAddress((void**)&t0, g_t0);
    cudaGetSymbolAddress((void**)&t0T, g_t0T);
    cudaGetSymbolAddress((void**)&t1hi, g_t1hi);
    cudaGetSymbolAddress((void**)&t1lo, g_t1lo);
    cudaGetSymbolAddress((void**)&t2T, g_t2T);
    cudaGetSymbolAddress((void**)&ssum, g_ssum);
    cudaGetSymbolAddress((void**)&rn, g_rn);
    cudaGetSymbolAddress((void**)&dis, g_dis);
    cudaGetSymbolAddress((void**)&rnparts, g_rnparts);
    cudaGetSymbolAddress((void**)&colpart, g_colpart);
    float* colsq2 = rnparts + 64 * N_NODES;

    const int SM_N_SPLIT = 3 * 2 * (128 + 128) * LDSH * 2;   // 122880
    const int SM_W_PLAIN = 4 * (128 + 256) * LDSH * 2;       // 122880
    cudaFuncSetAttribute(mma_nt<3,8,128>, cudaFuncAttributeMaxDynamicSharedMemorySize, SM_N_SPLIT);
    cudaFuncSetAttribute(mma_nt<3,7,128>, cudaFuncAttributeMaxDynamicSharedMemorySize, SM_N_SPLIT);
    cudaFuncSetAttribute(mma_nt<1,0,256>, cudaFuncAttributeMaxDynamicSharedMemorySize, SM_W_PLAIN);
    cudaFuncSetAttribute(mma_nt<1,6,256>, cudaFuncAttributeMaxDynamicSharedMemorySize, SM_W_PLAIN);
    cudaFuncSetAttribute(gram_sym, cudaFuncAttributeMaxDynamicSharedMemorySize, SM_W_PLAIN);

    dim3 blk(256);
    dim3 tpb(32, 8);

    // ---- prep (batched) ----
    concat_bias_kernel<<<1, 256>>>(bm, bs, mb0, sb0, mb1, sb1, bcat);
    wprep_kernel<<<dim3(16, 16, 6), tpb>>>(Wm, Ws, mW0, sW0, mW1, sW1, wThi, wTlo);
    split_kernel<<<(N_NODES * F_DIM) / 256, blk>>>(x, xhi, xlo, N_NODES * F_DIM);
    cudaMemsetAsync(rnparts, 0, 96 * N_NODES * sizeof(float));

    // ---- projection: xms(hi/lo) = x @ [Wm||Ws] + [bm||bs] ----
    mma_nt<3,8,128><<<dim3(8, 32), blk, SM_N_SPLIT>>>(xhi, xlo, wThi, wTlo, nullptr, xmshi, xmslo,
        N_NODES, 1024, 512, 512, 512, 1024, bcat, nullptr, 0, 0, 0);

    // ---- row statistics -> fcat [m||cs], ssum ----
    rowstats_kernel<<<N_NODES, 256>>>(xmshi, xmslo, fcat, ssum);

    // ---- symmetric gram + fused ws (bf16 out) + rn partials (triangle grid) ----
    gram_sym<<<272, blk, SM_W_PLAIN>>>(fcat, M1b, ssum, rnparts, colsq2);
    rnreduce_kernel<<<N_NODES / 256, blk>>>(rnparts, rn);

    // ---- adjacency: adj + transpose-to-bf16 + colsum partials (fused) ----
    adjT_kernel<<<dim3(64, 64), blk>>>(M1b, rn, new_edge, eps, beta, delta, AnT, colpart);
    colsum2_kernel<<<N_NODES / 256, blk>>>(colpart, dis);

    // ---- encoder layer 1: feat GEMM writes t0T directly (dis-scaled, transposed) ----
    mma_nt<3,7,128><<<dim3(4, 32, 2), blk, SM_N_SPLIT>>>(xmshi, xmslo, wThi + 524288, wTlo + 524288,
        nullptr, t0T, nullptr, N_NODES, 512, 512, 1024, 512, N_NODES,
        nullptr, dis, 512, 262144, (long)512 * N_NODES);
    mma_nt<1,6,256><<<dim3(4, 32), blk, SM_W_PLAIN>>>(AnT, nullptr, t0T, nullptr, nullptr,
        t1hi, t1lo, N_NODES, 1024, N_NODES, N_NODES, N_NODES, 1024,
        bcat + 1024, dis, 0, 0, 0);

    // ---- encoder layer 2: feat GEMM writes t2T directly; split-K x2 adjacency ----
    mma_nt<3,7,128><<<dim3(2, 32, 2), blk, SM_N_SPLIT>>>(t1hi, t1lo, wThi + 1048576, wTlo + 1048576,
        nullptr, t2T, nullptr, N_NODES, 256, 512, 1024, 512, N_NODES,
        nullptr, dis, 512, 131072, (long)256 * N_NODES);
    mma_nt<1,0,256><<<dim3(2, 32, 2), blk, SM_W_PLAIN>>>(AnT, nullptr, t2T, nullptr, t0,
        nullptr, nullptr, N_NODES, 512, 2048, N_NODES, N_NODES, 512,
        nullptr, nullptr, 2048, 2048, (long)N_NODES * 512);
    reduce_out_kernel<<<(N_NODES * 512) / 256, blk>>>(t0, bcat + 2048, dis, out);
}

// round 16
// speedup vs baseline: 1.0288x; 1.0288x over previous
#include <cuda_runtime.h>
#include <cuda_bf16.h>
#include <math.h>
#include <stdint.h>

#define N_NODES 4096
#define F_DIM   512
#define H_DIM   256

// ---------------- scratch (static device allocations; no runtime alloc) ----------
__device__ __align__(128) __nv_bfloat16 g_xhi[N_NODES * F_DIM];
__device__ __align__(128) __nv_bfloat16 g_xlo[N_NODES * F_DIM];
__device__ __align__(128) __nv_bfloat16 g_wThi[1310720];
__device__ __align__(128) __nv_bfloat16 g_wTlo[1310720];
__device__ __align__(128) float g_bcat[2560];
__device__ __align__(128) __nv_bfloat16 g_xmshi[N_NODES * 1024];
__device__ __align__(128) __nv_bfloat16 g_xmslo[N_NODES * 1024];
__device__ __align__(128) __nv_bfloat16 g_fcat[N_NODES * 1024];
__device__ __align__(128) __nv_bfloat16 g_M1b[(size_t)N_NODES * N_NODES];
__device__ __align__(128) __nv_bfloat16 g_AnT[(size_t)N_NODES * N_NODES];
__device__ __align__(128) float g_t0[N_NODES * 1024];          // split-K partials (enc2)
__device__ __align__(128) __nv_bfloat16 g_t0T[1024 * N_NODES];
__device__ __align__(128) __nv_bfloat16 g_t1hi[N_NODES * 1024];
__device__ __align__(128) __nv_bfloat16 g_t1lo[N_NODES * 1024];
__device__ __align__(128) __nv_bfloat16 g_t2T[512 * N_NODES];
__device__ __align__(128) float g_ssum[N_NODES];
__device__ __align__(128) float g_rn[N_NODES];
__device__ __align__(128) float g_dis[N_NODES];
__device__ __align__(128) float g_rnparts[96 * N_NODES];   // [0,64) row partials, [64,96) mirror col partials
__device__ __align__(128) float g_colpart[256 * N_NODES];

// ================= low-level helpers (sm_80+ features only) =================
__device__ __forceinline__ uint32_t smem_u32(const void* p) {
    uint32_t a;
    asm("{ .reg .u64 t; cvta.to.shared.u64 t, %1; cvt.u32.u64 %0, t; }" : "=r"(a) : "l"(p));
    return a;
}

#define CP_ASYNC_CG(dst, src) \
    asm volatile("cp.async.cg.shared.global [%0], [%1], 16;" :: "r"(dst), "l"(src))
#define CP_COMMIT() asm volatile("cp.async.commit_group;" ::: "memory")
#define CP_WAIT(n)  asm volatile("cp.async.wait_group %0;" :: "n"(n) : "memory")

__device__ __forceinline__ void ldmat_x4(uint32_t& r0, uint32_t& r1, uint32_t& r2, uint32_t& r3,
                                         uint32_t addr) {
    asm volatile("ldmatrix.sync.aligned.m8n8.x4.shared.b16 {%0,%1,%2,%3}, [%4];"
                 : "=r"(r0), "=r"(r1), "=r"(r2), "=r"(r3) : "r"(addr));
}

__device__ __forceinline__ void mma16816f(float* c, const uint32_t* a, const uint32_t* b) {
    asm volatile(
        "mma.sync.aligned.m16n8k16.row.col.f32.bf16.bf16.f32 "
        "{%0,%1,%2,%3}, {%4,%5,%6,%7}, {%8,%9}, {%0,%1,%2,%3};"
        : "+f"(c[0]), "+f"(c[1]), "+f"(c[2]), "+f"(c[3])
        : "r"(a[0]), "r"(a[1]), "r"(a[2]), "r"(a[3]), "r"(b[0]), "r"(b[1]));
}

#define BM 128
#define BK 32
#define LDSH 40   // BK + 8 halves padding

// ================= generalized bf16 HMMA NT GEMM =================
// C[M,N] = A[M,K] @ B[N,K]^T. bf16 K-major inputs.
// SPLIT==3: near-fp32 via AhiBhi + AhiBlo + AloBhi (BNT=128 only). 2-stage pipeline.
// SPLIT==1: 3-stage pipeline.  (2 CTAs/SM at these smem sizes — do not deepen.)
// EPI: 0=store fp32
//      6=*dis[row]+bias+relu, store hi/lo bf16
//      7=*dis[row], smem-transposed bf16 store to Ohi (ldc = transposed row length)
//      8=+bias, store hi/lo bf16 only
template<int SPLIT, int EPI, int BNT>
__global__ __launch_bounds__(256)
void mma_nt(const __nv_bfloat16* __restrict__ Ahi, const __nv_bfloat16* __restrict__ Alo,
            const __nv_bfloat16* __restrict__ Bhi, const __nv_bfloat16* __restrict__ Blo,
            float* __restrict__ C, __nv_bfloat16* __restrict__ Ohi, __nv_bfloat16* __restrict__ Olo,
            int M, int N, int K, int lda, int ldb, int ldc,
            const float* __restrict__ bias, const float* __restrict__ dis,
            long zA, long zB, long zC)
{
    constexpr int STAGES = (SPLIT == 1) ? 3 : 2;
    constexpr int WN     = BNT / 4;
    constexpr int NFR    = WN / 8;
    constexpr int TILEA  = BM * LDSH;
    constexpr int TILEB  = BNT * LDSH;
    constexpr int STAGE  = ((SPLIT == 3) ? 2 : 1) * (TILEA + TILEB);
    extern __shared__ __nv_bfloat16 smB[];

    const int tid  = threadIdx.x;
    const int wid  = tid >> 5;
    const int lane = tid & 31;
    const int wm = (wid & 1) * 64;
    const int wn = (wid >> 1) * WN;
    const int bm = blockIdx.y * BM;
    const int bn = blockIdx.x * BNT;

    const __nv_bfloat16* Ag  = Ahi + (size_t)blockIdx.z * zA + (size_t)bm * lda;
    const __nv_bfloat16* Bg  = Bhi + (size_t)blockIdx.z * zB + (size_t)bn * ldb;
    const __nv_bfloat16* Agl = (SPLIT == 3) ? Alo + (size_t)blockIdx.z * zA + (size_t)bm * lda : nullptr;
    const __nv_bfloat16* Bgl = (SPLIT == 3) ? Blo + (size_t)blockIdx.z * zB + (size_t)bn * ldb : nullptr;
    float* Cz = C + (size_t)blockIdx.z * zC;

    const uint32_t s_base = smem_u32(smB);
    const int lr0 = tid >> 2;
    const int lc  = (tid & 3) * 8;

    float acc[4][NFR][4];
    #pragma unroll
    for (int i = 0; i < 4; ++i)
        #pragma unroll
        for (int j = 0; j < NFR; ++j)
            #pragma unroll
            for (int q = 0; q < 4; ++q) acc[i][j][q] = 0.f;

    const int nt = K / BK;

    auto load_stage = [&](int st, int t) {
        const size_t kb = (size_t)t * BK + lc;
        const uint32_t sb = s_base + (uint32_t)(st * STAGE) * 2;
        #pragma unroll
        for (int h = 0; h < 2; ++h) {
            const int r = lr0 + h * 64;
            const uint32_t so = (uint32_t)(r * LDSH + lc) * 2;
            CP_ASYNC_CG(sb + so, Ag + (size_t)r * lda + kb);
            if (SPLIT == 3)
                CP_ASYNC_CG(sb + (uint32_t)(TILEA + TILEB) * 2 + so, Agl + (size_t)r * lda + kb);
        }
        #pragma unroll
        for (int h = 0; h < BNT / 64; ++h) {
            const int r = lr0 + h * 64;
            const uint32_t so = (uint32_t)(TILEA + r * LDSH + lc) * 2;
            CP_ASYNC_CG(sb + so, Bg + (size_t)r * ldb + kb);
            if (SPLIT == 3)
                CP_ASYNC_CG(sb + (uint32_t)(TILEA + TILEB) * 2 + so, Bgl + (size_t)r * ldb + kb);
        }
    };

    #pragma unroll
    for (int s = 0; s < STAGES - 1; ++s) { load_stage(s, s); CP_COMMIT(); }

    for (int t = 0; t < nt; ++t) {
        CP_WAIT(STAGES - 2);
        __syncthreads();
        if (t + STAGES - 1 < nt) { load_stage((t + STAGES - 1) % STAGES, t + STAGES - 1); CP_COMMIT(); }

        const uint32_t sb = s_base + (uint32_t)((t % STAGES) * STAGE) * 2;
        #pragma unroll
        for (int kk = 0; kk < BK; kk += 16) {
            uint32_t ah[4][4], al[4][4];
            #pragma unroll
            for (int mf = 0; mf < 4; ++mf) {
                int row = wm + mf * 16 + (lane & 15);
                uint32_t off = (uint32_t)(row * LDSH + kk + ((lane >> 4) << 3)) * 2;
                ldmat_x4(ah[mf][0], ah[mf][1], ah[mf][2], ah[mf][3], sb + off);
                if (SPLIT == 3)
                    ldmat_x4(al[mf][0], al[mf][1], al[mf][2], al[mf][3],
                             sb + (uint32_t)(TILEA + TILEB) * 2 + off);
            }
            uint32_t bh[NFR][2], bl[NFR][2];
            #pragma unroll
            for (int nf2 = 0; nf2 < NFR / 2; ++nf2) {
                int row = wn + nf2 * 16 + (lane & 7) + (((lane >> 4) & 1) << 3);
                uint32_t off = (uint32_t)(TILEA + row * LDSH + kk + (((lane >> 3) & 1) << 3)) * 2;
                uint32_t r0, r1, r2, r3;
                ldmat_x4(r0, r1, r2, r3, sb + off);
                bh[nf2 * 2 + 0][0] = r0; bh[nf2 * 2 + 0][1] = r1;
                bh[nf2 * 2 + 1][0] = r2; bh[nf2 * 2 + 1][1] = r3;
                if (SPLIT == 3) {
                    ldmat_x4(r0, r1, r2, r3, sb + (uint32_t)(TILEA + TILEB) * 2 + off);
                    bl[nf2 * 2 + 0][0] = r0; bl[nf2 * 2 + 0][1] = r1;
                    bl[nf2 * 2 + 1][0] = r2; bl[nf2 * 2 + 1][1] = r3;
                }
            }
            #pragma unroll
            for (int mf = 0; mf < 4; ++mf)
                #pragma unroll
                for (int nf = 0; nf < NFR; ++nf) {
                    mma16816f(acc[mf][nf], ah[mf], bh[nf]);
                    if (SPLIT == 3) {
                        mma16816f(acc[mf][nf], ah[mf], bl[nf]);
                        mma16816f(acc[mf][nf], al[mf], bh[nf]);
                    }
                }
        }
        // no trailing sync: next iter's loads are gated by the top-of-loop barrier
    }

    if (EPI == 7) {
        // ---- transposed bf16 epilogue: Ohi[(bn+c)*ldc + bm+r] = acc[r][c] * dis[bm+r] ----
        __syncthreads();   // all warps done reading pipeline smem
        __nv_bfloat16* st = smB;   // BNT x 136 halves
        #pragma unroll
        for (int mf = 0; mf < 4; ++mf) {
            int rl = wm + mf * 16 + (lane >> 2);
            float d0 = dis[bm + rl], d1 = dis[bm + rl + 8];
            #pragma unroll
            for (int nf = 0; nf < NFR; ++nf) {
                int cl = wn + nf * 8 + (lane & 3) * 2;
                st[(cl + 0) * 136 + rl]     = __float2bfloat16(acc[mf][nf][0] * d0);
                st[(cl + 1) * 136 + rl]     = __float2bfloat16(acc[mf][nf][1] * d0);
                st[(cl + 0) * 136 + rl + 8] = __float2bfloat16(acc[mf][nf][2] * d1);
                st[(cl + 1) * 136 + rl + 8] = __float2bfloat16(acc[mf][nf][3] * d1);
            }
        }
        __syncthreads();
        __nv_bfloat16* Ohz = Ohi + (size_t)blockIdx.z * zC;
        for (int it = tid; it < BNT * 16; it += 256) {
            int c = it >> 4, ch = it & 15;
            uint4 v = *(uint4*)&st[c * 136 + ch * 8];
            *(uint4*)(Ohz + (size_t)(bn + c) * ldc + bm + ch * 8) = v;
        }
        return;
    }

    // ---- register epilogues ----
    #pragma unroll
    for (int mf = 0; mf < 4; ++mf) {
        #pragma unroll
        for (int nf = 0; nf < NFR; ++nf) {
            int rg = bm + wm + mf * 16 + (lane >> 2);
            int cg = bn + wn + nf * 8 + (lane & 3) * 2;
            float v0 = acc[mf][nf][0], v1 = acc[mf][nf][1];
            float v2 = acc[mf][nf][2], v3 = acc[mf][nf][3];
            if (EPI == 8) {
                float b0 = bias[cg], b1 = bias[cg + 1];
                v0 += b0; v1 += b1; v2 += b0; v3 += b1;
            }
            if (EPI == 6) {
                float d0 = dis[rg], d1 = dis[rg + 8];
                float b0 = bias[cg], b1 = bias[cg + 1];
                v0 = fmaxf(fmaf(v0, d0, b0), 0.f);
                v1 = fmaxf(fmaf(v1, d0, b1), 0.f);
                v2 = fmaxf(fmaf(v2, d1, b0), 0.f);
                v3 = fmaxf(fmaf(v3, d1, b1), 0.f);
            }
            if (EPI == 6 || EPI == 8) {
                __nv_bfloat162 h01, l01, h23, l23;
                h01.x = __float2bfloat16(v0); h01.y = __float2bfloat16(v1);
                l01.x = __float2bfloat16(v0 - __bfloat162float(h01.x));
                l01.y = __float2bfloat16(v1 - __bfloat162float(h01.y));
                h23.x = __float2bfloat16(v2); h23.y = __float2bfloat16(v3);
                l23.x = __float2bfloat16(v2 - __bfloat162float(h23.x));
                l23.y = __float2bfloat16(v3 - __bfloat162float(h23.y));
                *(__nv_bfloat162*)(Ohi + (size_t)rg * ldc + cg) = h01;
                *(__nv_bfloat162*)(Olo + (size_t)rg * ldc + cg) = l01;
                *(__nv_bfloat162*)(Ohi + (size_t)(rg + 8) * ldc + cg) = h23;
                *(__nv_bfloat162*)(Olo + (size_t)(rg + 8) * ldc + cg) = l23;
            } else {
                float2 p0; p0.x = v0; p0.y = v1;
                float2 p1; p1.x = v2; p1.y = v3;
                *(float2*)(Cz + (size_t)rg * ldc + cg) = p0;
                *(float2*)(Cz + (size_t)(rg + 8) * ldc + cg) = p1;
            }
        }
    }
}

// ================= symmetric gram + ws + rn partials (triangle grid, 3-stage) =========
__global__ __launch_bounds__(256)
void gram_sym(const __nv_bfloat16* __restrict__ A, __nv_bfloat16* __restrict__ M1b,
              const float* __restrict__ ssum, float* __restrict__ rnpart,
              float* __restrict__ colsq2)
{
    constexpr int NFR = 8;
    constexpr int TILEA = 128 * LDSH, TILEB = 256 * LDSH, STAGE = TILEA + TILEB;
    extern __shared__ __nv_bfloat16 smB[];
    __nv_bfloat16* mir = smB;                              // 256 x 136 halves
    float* colsq = (float*)((char*)smB + 69632);           // 256 floats

    int L = blockIdx.x, p = 0;
    while (L >= 2 * (16 - p)) { L -= 2 * (16 - p); ++p; }
    int m, b;
    if (L < 16 - p) { m = 2 * p; b = p + L; }
    else            { m = 2 * p + 1; b = p + L - (16 - p); }
    const int bm = m * 128, bn = b * 256;
    const bool above = (2 * b >= m + 1);

    const int tid  = threadIdx.x;
    const int wid  = tid >> 5;
    const int lane = tid & 31;
    const int wm = (wid & 1) * 64;
    const int wn = (wid >> 1) * 64;

    const __nv_bfloat16* Ag = A + (size_t)bm * 1024;
    const __nv_bfloat16* Bg = A + (size_t)bn * 1024;
    const uint32_t s_base = smem_u32(smB);
    const int lr0 = tid >> 2;
    const int lc  = (tid & 3) * 8;

    float acc[4][NFR][4];
    #pragma unroll
    for (int i = 0; i < 4; ++i)
        #pragma unroll
        for (int j = 0; j < NFR; ++j)
            #pragma unroll
            for (int q = 0; q < 4; ++q) acc[i][j][q] = 0.f;

    auto load_stage = [&](int st, int t) {
        const size_t kb = (size_t)t * BK + lc;
        const uint32_t sb = s_base + (uint32_t)(st * STAGE) * 2;
        #pragma unroll
        for (int h = 0; h < 2; ++h) {
            const int r = lr0 + h * 64;
            CP_ASYNC_CG(sb + (uint32_t)(r * LDSH + lc) * 2, Ag + (size_t)r * 1024 + kb);
        }
        #pragma unroll
        for (int h = 0; h < 4; ++h) {
            const int r = lr0 + h * 64;
            CP_ASYNC_CG(sb + (uint32_t)(TILEA + r * LDSH + lc) * 2, Bg + (size_t)r * 1024 + kb);
        }
    };

    #pragma unroll
    for (int s = 0; s < 2; ++s) { load_stage(s, s); CP_COMMIT(); }

    for (int t = 0; t < 32; ++t) {
        CP_WAIT(1);
        __syncthreads();
        if (t + 2 < 32) { load_stage((t + 2) % 3, t + 2); CP_COMMIT(); }

        const uint32_t sb = s_base + (uint32_t)((t % 3) * STAGE) * 2;
        #pragma unroll
        for (int kk = 0; kk < BK; kk += 16) {
            uint32_t ah[4][4];
            #pragma unroll
            for (int mf = 0; mf < 4; ++mf) {
                int row = wm + mf * 16 + (lane & 15);
                uint32_t off = (uint32_t)(row * LDSH + kk + ((lane >> 4) << 3)) * 2;
                ldmat_x4(ah[mf][0], ah[mf][1], ah[mf][2], ah[mf][3], sb + off);
            }
            uint32_t bh[NFR][2];
            #pragma unroll
            for (int nf2 = 0; nf2 < NFR / 2; ++nf2) {
                int row = wn + nf2 * 16 + (lane & 7) + (((lane >> 4) & 1) << 3);
                uint32_t off = (uint32_t)(TILEA + row * LDSH + kk + (((lane >> 3) & 1) << 3)) * 2;
                uint32_t r0, r1, r2, r3;
                ldmat_x4(r0, r1, r2, r3, sb + off);
                bh[nf2 * 2 + 0][0] = r0; bh[nf2 * 2 + 0][1] = r1;
                bh[nf2 * 2 + 1][0] = r2; bh[nf2 * 2 + 1][1] = r3;
            }
            #pragma unroll
            for (int mf = 0; mf < 4; ++mf)
                #pragma unroll
                for (int nf = 0; nf < NFR; ++nf)
                    mma16816f(acc[mf][nf], ah[mf], bh[nf]);
        }
    }
    __syncthreads();   // protect smem reuse (mir/colsq alias pipeline buffers)

    if (above) colsq[tid] = 0.f;
    __syncthreads();

    float rs[8];
    #pragma unroll
    for (int i = 0; i < 8; ++i) rs[i] = 0.f;
    float cs0[NFR], cs1[NFR];
    #pragma unroll
    for (int i = 0; i < NFR; ++i) { cs0[i] = 0.f; cs1[i] = 0.f; }

    #pragma unroll
    for (int mf = 0; mf < 4; ++mf) {
        #pragma unroll
        for (int nf = 0; nf < NFR; ++nf) {
            int rl = wm + mf * 16 + (lane >> 2);
            int cl = wn + nf * 8 + (lane & 3) * 2;
            int rg = bm + rl, cg = bn + cl;
            float sc0 = ssum[cg], sc1 = ssum[cg + 1];
            float sr0 = ssum[rg], sr1 = ssum[rg + 8];
            float v0 = expf(2.f * acc[mf][nf][0] - sr0 - sc0);
            float v1 = expf(2.f * acc[mf][nf][1] - sr0 - sc1);
            float v2 = expf(2.f * acc[mf][nf][2] - sr1 - sc0);
            float v3 = expf(2.f * acc[mf][nf][3] - sr1 - sc1);
            rs[mf * 2 + 0] = fmaf(v0, v0, fmaf(v1, v1, rs[mf * 2 + 0]));
            rs[mf * 2 + 1] = fmaf(v2, v2, fmaf(v3, v3, rs[mf * 2 + 1]));
            __nv_bfloat162 h01, h23;
            h01.x = __float2bfloat16(v0); h01.y = __float2bfloat16(v1);
            h23.x = __float2bfloat16(v2); h23.y = __float2bfloat16(v3);
            *(__nv_bfloat162*)(M1b + (size_t)rg * N_NODES + cg) = h01;
            *(__nv_bfloat162*)(M1b + (size_t)(rg + 8) * N_NODES + cg) = h23;
            if (above) {
                cs0[nf] = fmaf(v0, v0, fmaf(v2, v2, cs0[nf]));
                cs1[nf] = fmaf(v1, v1, fmaf(v3, v3, cs1[nf]));
                mir[(cl + 0) * 136 + rl]     = h01.x;
                mir[(cl + 1) * 136 + rl]     = h01.y;
                mir[(cl + 0) * 136 + rl + 8] = h23.x;
                mir[(cl + 1) * 136 + rl + 8] = h23.y;
            }
        }
    }

    #pragma unroll
    for (int i = 0; i < 8; ++i) {
        rs[i] += __shfl_xor_sync(0xffffffffu, rs[i], 1);
        rs[i] += __shfl_xor_sync(0xffffffffu, rs[i], 2);
    }
    if ((lane & 3) == 0) {
        int pidx = b * 4 + (wid >> 1);
        #pragma unroll
        for (int mf = 0; mf < 4; ++mf) {
            int row = bm + wm + mf * 16 + (lane >> 2);
            rnpart[(size_t)pidx * N_NODES + row]     = rs[mf * 2 + 0];
            rnpart[(size_t)pidx * N_NODES + row + 8] = rs[mf * 2 + 1];
        }
    }

    if (above) {
        #pragma unroll
        for (int nf = 0; nf < NFR; ++nf) {
            #pragma unroll
            for (int o = 4; o < 32; o <<= 1) {
                cs0[nf] += __shfl_xor_sync(0xffffffffu, cs0[nf], o);
                cs1[nf] += __shfl_xor_sync(0xffffffffu, cs1[nf], o);
            }
        }
        if (lane < 4) {
            #pragma unroll
            for (int nf = 0; nf < NFR; ++nf) {
                atomicAdd(&colsq[wn + nf * 8 + lane * 2], cs0[nf]);
                atomicAdd(&colsq[wn + nf * 8 + lane * 2 + 1], cs1[nf]);
            }
        }
        __syncthreads();
        #pragma unroll 4
        for (int it = 0; it < 64; ++it) {
            int c = it * 4 + (tid >> 6);
            uint32_t vv = *(uint32_t*)&mir[c * 136 + (tid & 63) * 2];
            *(uint32_t*)(M1b + (size_t)(bn + c) * N_NODES + bm + (tid & 63) * 2) = vv;
        }
        colsq2[(size_t)m * N_NODES + bn + tid] = colsq[tid];
    }
}

// ---------------- batched weight prep: 6 transposes+splits in one launch ----------------
__global__ void wprep_kernel(const float* __restrict__ Wm, const float* __restrict__ Ws,
                             const float* __restrict__ mW0, const float* __restrict__ sW0,
                             const float* __restrict__ mW1, const float* __restrict__ sW1,
                             __nv_bfloat16* __restrict__ wThi, __nv_bfloat16* __restrict__ wTlo)
{
    const int z = blockIdx.z;
    const float* in; int C; long off;
    switch (z) {
        case 0:  in = Wm;  C = 512; off = 0;       break;
        case 1:  in = Ws;  C = 512; off = 262144;  break;
        case 2:  in = mW0; C = 512; off = 524288;  break;
        case 3:  in = sW0; C = 512; off = 786432;  break;
        case 4:  in = mW1; C = 256; off = 1048576; break;
        default: in = sW1; C = 256; off = 1179648; break;
    }
    if (blockIdx.x * 32 >= C) return;
    const int R = 512;
    __shared__ float t[32][33];
    int r0 = blockIdx.y * 32, c0 = blockIdx.x * 32;
    int tx = threadIdx.x, ty = threadIdx.y;
    #pragma unroll
    for (int j = 0; j < 4; ++j)
        t[ty + j * 8][tx] = in[(size_t)(r0 + ty + j * 8) * C + c0 + tx];
    __syncthreads();
    #pragma unroll
    for (int j = 0; j < 4; ++j) {
        int c = c0 + ty + j * 8;
        float v = t[tx][ty + j * 8];
        __nv_bfloat16 h = __float2bfloat16(v);
        __nv_bfloat16 l = __float2bfloat16(v - __bfloat162float(h));
        wThi[off + (size_t)c * R + r0 + tx] = h;
        wTlo[off + (size_t)c * R + r0 + tx] = l;
    }
}

__global__ void split_kernel(const float* __restrict__ in, __nv_bfloat16* __restrict__ ohi,
                             __nv_bfloat16* __restrict__ olo, int n)
{
    int idx = blockIdx.x * 256 + threadIdx.x;
    if (idx < n) {
        float v = in[idx];
        __nv_bfloat16 h = __float2bfloat16(v);
        ohi[idx] = h;
        olo[idx] = __float2bfloat16(v - __bfloat162float(h));
    }
}

__global__ void concat_bias_kernel(const float* bm, const float* bs, const float* mb0,
                                   const float* sb0, const float* mb1, const float* sb1,
                                   float* __restrict__ bcat)
{
    for (int i = threadIdx.x; i < 2560; i += blockDim.x) {
        float v;
        if (i < 512)        v = bm[i];
        else if (i < 1024)  v = bs[i - 512];
        else if (i < 1536)  v = mb0[i - 1024];
        else if (i < 2048)  v = sb0[i - 1536];
        else if (i < 2304)  v = mb1[i - 2048];
        else                v = sb1[i - 2304];
        bcat[i] = v;
    }
}

// ---------------- block reduction ----------------
__device__ __forceinline__ float blockReduceSum(float v, float* sh) {
    __syncthreads();
    int lane = threadIdx.x & 31, wid = threadIdx.x >> 5;
    #pragma unroll
    for (int o = 16; o; o >>= 1) v += __shfl_down_sync(0xffffffffu, v, o);
    if (lane == 0) sh[wid] = v;
    __syncthreads();
    if (wid == 0) {
        float r = (lane < ((blockDim.x + 31) >> 5)) ? sh[lane] : 0.f;
        #pragma unroll
        for (int o = 16; o; o >>= 1) r += __shfl_down_sync(0xffffffffu, r, o);
        if (lane == 0) sh[0] = r;
    }
    __syncthreads();
    return sh[0];
}

// ---------------- per-row stats from xms hi/lo: fcat = [m_hat||cs_hat], ssum ----
__global__ void rowstats_kernel(const __nv_bfloat16* __restrict__ xmshi,
                                const __nv_bfloat16* __restrict__ xmslo,
                                __nv_bfloat16* __restrict__ fcat, float* __restrict__ ssum)
{
    __shared__ float sh[32];
    int row = blockIdx.x;
    const __nv_bfloat16* hi = xmshi + (size_t)row * 1024;
    const __nv_bfloat16* lo = xmslo + (size_t)row * 1024;
    float s1 = 0.f, s2 = 0.f, s3 = 0.f;
    for (int j = threadIdx.x; j < F_DIM; j += blockDim.x) {
        float a = __bfloat162float(hi[j]) + __bfloat162float(lo[j]);
        s1 = fmaf(a, a, s1);
        float xs = __bfloat162float(hi[512 + j]) + __bfloat162float(lo[512 + j]);
        float e = expf(xs); s2 = fmaf(e, e, s2); s3 += e;
    }
    s1 = blockReduceSum(s1, sh);
    s2 = blockReduceSum(s2, sh);
    s3 = blockReduceSum(s3, sh);
    float dm = fmaxf(sqrtf(s1), 1e-12f);
    float dc = fmaxf(sqrtf(s2), 1e-12f);
    if (threadIdx.x == 0) ssum[row] = s1 / (dm * dm) + s3 / dc;
    float rdm = 1.f / dm;
    float rqc = rsqrtf(dc);
    for (int j = threadIdx.x; j < F_DIM; j += blockDim.x) {
        float a = __bfloat162float(hi[j]) + __bfloat162float(lo[j]);
        float xs = __bfloat162float(hi[512 + j]) + __bfloat162float(lo[512 + j]);
        fcat[(size_t)row * 1024 + j]       = __float2bfloat16(a * rdm);
        fcat[(size_t)row * 1024 + 512 + j] = __float2bfloat16(expf(0.5f * xs) * rqc);
    }
}

__global__ void rnreduce_kernel(const float* __restrict__ rnparts, float* __restrict__ rn) {
    int row = blockIdx.x * 256 + threadIdx.x;
    float s0 = 0.f, s1 = 0.f, s2 = 0.f, s3 = 0.f;
    #pragma unroll
    for (int p = 0; p < 96; p += 4) {
        s0 += rnparts[(size_t)(p + 0) * N_NODES + row];
        s1 += rnparts[(size_t)(p + 1) * N_NODES + row];
        s2 += rnparts[(size_t)(p + 2) * N_NODES + row];
        s3 += rnparts[(size_t)(p + 3) * N_NODES + row];
    }
    rn[row] = 1.f / fmaxf(sqrtf((s0 + s1) + (s2 + s3)), 1e-12f);
}

// ---------------- fused adjacency + bf16-transpose + column partials ----------------
__global__ __launch_bounds__(256)
void adjT_kernel(const __nv_bfloat16* __restrict__ M1b, const float* __restrict__ rn,
                 const float* __restrict__ ne, const float* __restrict__ epsm,
                 const float* __restrict__ beta, const float* __restrict__ delta,
                 __nv_bfloat16* __restrict__ AnT, float* __restrict__ colpart)
{
    __shared__ __nv_bfloat16 tileT[64][66];
    const int c0 = blockIdx.x * 64, r0 = blockIdx.y * 64;
    const int t = threadIdx.x;
    const int jl = t & 63, ig = t >> 6;
    const int j = c0 + jl;
    const float b = beta[0], d = delta[0];
    float s = 0.f;
    #pragma unroll 4
    for (int k = 0; k < 16; ++k) {
        const int il = ig + 4 * k;
        const int i = r0 + il;
        const size_t idx = (size_t)i * N_NODES + j;
        float w = __bfloat162float(M1b[idx]) * rn[i];
        float tt = (1.f - b) * w + b * ne[idx];
        tt = fminf(fmaxf(tt, 1e-6f), 1.f - 1e-6f);
        float e = fminf(fmaxf(epsm[idx], 1e-6f), 1.f - 1e-6f);
        float num = tt * e;
        float sg = num / (num + (1.f - tt) * (1.f - e));
        float a = (sg > d) ? sg : 0.f;
        if (i == j && !(a > 0.f)) a += 1.f;
        tileT[il][jl] = __float2bfloat16(a);
        s += a;
    }
    colpart[(size_t)(blockIdx.y * 4 + ig) * N_NODES + j] = s;
    __syncthreads();
    const int il2 = t & 63;
    #pragma unroll
    for (int jj = t >> 6; jj < 64; jj += 4)
        AnT[(size_t)(c0 + jj) * N_NODES + r0 + il2] = tileT[il2][jj];
}

__global__ void colsum2_kernel(const float* __restrict__ part, float* __restrict__ dis) {
    int j = blockIdx.x * 256 + threadIdx.x;
    float s0 = 0.f, s1 = 0.f, s2 = 0.f, s3 = 0.f;
    for (int p = 0; p < 256; p += 4) {
        s0 += part[(size_t)(p + 0) * N_NODES + j];
        s1 += part[(size_t)(p + 1) * N_NODES + j];
        s2 += part[(size_t)(p + 2) * N_NODES + j];
        s3 += part[(size_t)(p + 3) * N_NODES + j];
    }
    float s = (s0 + s1) + (s2 + s3);
    dis[j] = (s > 0.f) ? (1.f / sqrtf(s)) : 0.f;
}

// ---------------- split-K reduce + dis + bias + relu + z-split output ----------------
__global__ void reduce_out_kernel(const float* __restrict__ part, const float* __restrict__ bias,
                                  const float* __restrict__ dis, float* __restrict__ out)
{
    int idx = blockIdx.x * 256 + threadIdx.x;   // over 4096*512
    int row = idx >> 9, col = idx & 511;
    float v = fmaf(part[idx] + part[idx + N_NODES * 512], dis[row], bias[col]);
    v = fmaxf(v, 0.f);
    out[(size_t)(col >> 8) * (N_NODES * H_DIM) + (size_t)row * H_DIM + (col & 255)] = v;
}

// ---------------- host ----------------
extern "C" void kernel_launch(void* const* d_in, const int* in_sizes, int n_in,
                              void* d_out, int out_size)
{
    const float* x        = (const float*)d_in[0];
    const float* new_edge = (const float*)d_in[1];
    const float* beta     = (const float*)d_in[2];
    const float* delta    = (const float*)d_in[3];
    const float* eps      = (const float*)d_in[4];
    const float* Wm       = (const float*)d_in[5];
    const float* bm       = (const float*)d_in[6];
    const float* Ws       = (const float*)d_in[7];
    const float* bs       = (const float*)d_in[8];
    const float* mW0      = (const float*)d_in[9];
    const float* mb0      = (const float*)d_in[10];
    const float* mW1      = (const float*)d_in[11];
    const float* mb1      = (const float*)d_in[12];
    const float* sW0      = (const float*)d_in[13];
    const float* sb0      = (const float*)d_in[14];
    const float* sW1      = (const float*)d_in[15];
    const float* sb1      = (const float*)d_in[16];
    float* out = (float*)d_out;

    float *t0, *ssum, *rn, *dis, *rnparts, *colpart, *bcat;
    __nv_bfloat16 *xhi, *xlo, *wThi, *wTlo, *xmshi, *xmslo, *fcat, *M1b, *AnT, *t0T, *t1hi, *t1lo, *t2T;
    cudaGetSymbolAddress((void**)&xhi, g_xhi);
    cudaGetSymbolAddress((void**)&xlo, g_xlo);
    cudaGetSymbolAddress((void**)&wThi, g_wThi);
    cudaGetSymbolAddress((void**)&wTlo, g_wTlo);
    cudaGetSymbolAddress((void**)&bcat, g_bcat);
    cudaGetSymbolAddress((void**)&xmshi, g_xmshi);
    cudaGetSymbolAddress((void**)&xmslo, g_xmslo);
    cudaGetSymbolAddress((void**)&fcat, g_fcat);
    cudaGetSymbolAddress((void**)&M1b, g_M1b);
    cudaGetSymbolAddress((void**)&AnT, g_AnT);
    cudaGetSymbolAddress((void**)&t0, g_t0);
    cudaGetSymbolAddress((void**)&t0T, g_t0T);
    cudaGetSymbolAddress((void**)&t1hi, g_t1hi);
    cudaGetSymbolAddress((void**)&t1lo, g_t1lo);
    cudaGetSymbolAddress((void**)&t2T, g_t2T);
    cudaGetSymbolAddress((void**)&ssum, g_ssum);
    cudaGetSymbolAddress((void**)&rn, g_rn);
    cudaGetSymbolAddress((void**)&dis, g_dis);
    cudaGetSymbolAddress((void**)&rnparts, g_rnparts);
    cudaGetSymbolAddress((void**)&colpart, g_colpart);
    float* colsq2 = rnparts + 64 * N_NODES;

    const int SM_N_SPLIT = 2 * 2 * (128 + 128) * LDSH * 2;   // 81920  (2 CTAs/SM)
    const int SM_W_PLAIN = 3 * (128 + 256) * LDSH * 2;       // 92160  (2 CTAs/SM)
    cudaFuncSetAttribute(mma_nt<3,8,128>, cudaFuncAttributeMaxDynamicSharedMemorySize, SM_N_SPLIT);
    cudaFuncSetAttribute(mma_nt<3,7,128>, cudaFuncAttributeMaxDynamicSharedMemorySize, SM_N_SPLIT);
    cudaFuncSetAttribute(mma_nt<1,0,256>, cudaFuncAttributeMaxDynamicSharedMemorySize, SM_W_PLAIN);
    cudaFuncSetAttribute(mma_nt<1,6,256>, cudaFuncAttributeMaxDynamicSharedMemorySize, SM_W_PLAIN);
    cudaFuncSetAttribute(gram_sym, cudaFuncAttributeMaxDynamicSharedMemorySize, SM_W_PLAIN);

    dim3 blk(256);
    dim3 tpb(32, 8);

    // ---- prep (batched) ----
    concat_bias_kernel<<<1, 256>>>(bm, bs, mb0, sb0, mb1, sb1, bcat);
    wprep_kernel<<<dim3(16, 16, 6), tpb>>>(Wm, Ws, mW0, sW0, mW1, sW1, wThi, wTlo);
    split_kernel<<<(N_NODES * F_DIM) / 256, blk>>>(x, xhi, xlo, N_NODES * F_DIM);
    cudaMemsetAsync(rnparts, 0, 96 * N_NODES * sizeof(float));

    // ---- projection: xms(hi/lo) = x @ [Wm||Ws] + [bm||bs] ----
    mma_nt<3,8,128><<<dim3(8, 32), blk, SM_N_SPLIT>>>(xhi, xlo, wThi, wTlo, nullptr, xmshi, xmslo,
        N_NODES, 1024, 512, 512, 512, 1024, bcat, nullptr, 0, 0, 0);

    // ---- row statistics -> fcat [m||cs], ssum ----
    rowstats_kernel<<<N_NODES, 256>>>(xmshi, xmslo, fcat, ssum);

    // ---- symmetric gram + fused ws (bf16 out) + rn partials (triangle grid) ----
    gram_sym<<<272, blk, SM_W_PLAIN>>>(fcat, M1b, ssum, rnparts, colsq2);
    rnreduce_kernel<<<N_NODES / 256, blk>>>(rnparts, rn);

    // ---- adjacency: adj + transpose-to-bf16 + colsum partials (fused) ----
    adjT_kernel<<<dim3(64, 64), blk>>>(M1b, rn, new_edge, eps, beta, delta, AnT, colpart);
    colsum2_kernel<<<N_NODES / 256, blk>>>(colpart, dis);

    // ---- encoder layer 1: feat GEMM writes t0T directly (dis-scaled, transposed) ----
    mma_nt<3,7,128><<<dim3(4, 32, 2), blk, SM_N_SPLIT>>>(xmshi, xmslo, wThi + 524288, wTlo + 524288,
        nullptr, t0T, nullptr, N_NODES, 512, 512, 1024, 512, N_NODES,
        nullptr, dis, 512, 262144, (long)512 * N_NODES);
    mma_nt<1,6,256><<<dim3(4, 32), blk, SM_W_PLAIN>>>(AnT, nullptr, t0T, nullptr, nullptr,
        t1hi, t1lo, N_NODES, 1024, N_NODES, N_NODES, N_NODES, 1024,
        bcat + 1024, dis, 0, 0, 0);

    // ---- encoder layer 2: feat GEMM writes t2T directly; split-K x2 adjacency ----
    mma_nt<3,7,128><<<dim3(2, 32, 2), blk, SM_N_SPLIT>>>(t1hi, t1lo, wThi + 1048576, wTlo + 1048576,
        nullptr, t2T, nullptr, N_NODES, 256, 512, 1024, 512, N_NODES,
        nullptr, dis, 512, 131072, (long)256 * N_NODES);
    mma_nt<1,0,256><<<dim3(2, 32, 2), blk, SM_W_PLAIN>>>(AnT, nullptr, t2T, nullptr, t0,
        nullptr, nullptr, N_NODES, 512, 2048, N_NODES, N_NODES, 512,
        nullptr, nullptr, 2048, 2048, (long)N_NODES * 512);
    reduce_out_kernel<<<(N_NODES * 512) / 256, blk>>>(t0, bcat + 2048, dis, out);
}